// round 15
// baseline (speedup 1.0000x reference)
#include <cuda_runtime.h>
#include <cuda_fp16.h>
#include <cstdint>
#include <math.h>

#define D_MODEL 512
#define N_HEADS 8
#define DK      64
#define D_FF    2048
#define BATCH   2
#define SEQ     2048
#define NTOK    (BATCH * SEQ)   // 4096

#define SCALE_Q 0.18033688011112042f   // 0.125 * log2(e)

// ---------------- scratch (device globals; no allocation allowed) ----------
static __device__ float g_x1 [(size_t)NTOK * D_MODEL];
static __device__ float g_tmp[(size_t)NTOK * D_MODEL];

static __device__ __half g_xh [(size_t)NTOK * D_MODEL];
static __device__ __half g_qh [(size_t)NTOK * D_MODEL];
static __device__ __half g_kh [(size_t)NTOK * D_MODEL];
static __device__ __half g_vh [(size_t)NTOK * D_MODEL];
static __device__ __half g_ctx[(size_t)NTOK * D_MODEL];
static __device__ __half g_x1h[(size_t)NTOK * D_MODEL];
static __device__ __half g_ffh[(size_t)NTOK * D_FF];

// transposed fp16 weights: Wt[n][k]; WQ/WK/WV contiguous -> fused [1536,512]
#define OFF_WQKV 0
#define OFF_WO   (3*512*512)
#define OFF_W1   (4*512*512)
#define OFF_W2   (4*512*512 + 2048*512)
#define WT_TOTAL (4*512*512 + 2*2048*512)
static __device__ __half g_wt[WT_TOTAL];

// ======================= PTX helpers (base sm_80+ features) ================
__device__ __forceinline__ uint32_t smem_u32(const void* p) {
    uint32_t a;
    asm("{ .reg .u64 t; cvta.to.shared.u64 t, %1; cvt.u32.u64 %0, t; }"
        : "=r"(a) : "l"(p));
    return a;
}
__device__ __forceinline__ void cp_async16(uint32_t dst, const void* src) {
    asm volatile("cp.async.cg.shared.global [%0], [%1], 16;" :: "r"(dst), "l"(src));
}
#define CP_COMMIT() asm volatile("cp.async.commit_group;" ::: "memory")
#define CP_WAIT1()  asm volatile("cp.async.wait_group 1;" ::: "memory")
#define CP_WAIT2()  asm volatile("cp.async.wait_group 2;" ::: "memory")

__device__ __forceinline__ void ldm_x4(uint32_t* r, uint32_t addr) {
    asm volatile("ldmatrix.sync.aligned.m8n8.x4.shared.b16 {%0,%1,%2,%3}, [%4];"
        : "=r"(r[0]), "=r"(r[1]), "=r"(r[2]), "=r"(r[3]) : "r"(addr));
}
__device__ __forceinline__ void ldm_x4_t(uint32_t* r, uint32_t addr) {
    asm volatile("ldmatrix.sync.aligned.m8n8.x4.trans.shared.b16 {%0,%1,%2,%3}, [%4];"
        : "=r"(r[0]), "=r"(r[1]), "=r"(r[2]), "=r"(r[3]) : "r"(addr));
}
__device__ __forceinline__ void mma_f16(float* c, const uint32_t* a, const uint32_t* b) {
    asm volatile("mma.sync.aligned.m16n8k16.row.col.f32.f16.f16.f32 "
        "{%0,%1,%2,%3}, {%4,%5,%6,%7}, {%8,%9}, {%0,%1,%2,%3};"
        : "+f"(c[0]), "+f"(c[1]), "+f"(c[2]), "+f"(c[3])
        : "r"(a[0]), "r"(a[1]), "r"(a[2]), "r"(a[3]), "r"(b[0]), "r"(b[1]));
}
// pack (lo, hi) -> f16x2 (lo in low half)
__device__ __forceinline__ uint32_t pack_f16x2(float lo, float hi) {
    uint32_t r;
    asm("cvt.rn.f16x2.f32 %0, %1, %2;" : "=r"(r) : "f"(hi), "f"(lo));
    return r;
}
// packed fp16x2 exp2 on MUFU (sm_75+)
__device__ __forceinline__ uint32_t ex2_f16x2(uint32_t x) {
    uint32_t r;
    asm("ex2.approx.f16x2 %0, %1;" : "=r"(r) : "r"(x));
    return r;
}

// fast exp2 for x <= 0 on the FMA pipe (no MUFU). abs err ~2e-6.
__device__ __forceinline__ float exp2p(float x) {
    x = fmaxf(x, -126.f);
    float t = __fadd_rn(x, 12582912.f);
    float n = __fadd_rn(t, -12582912.f);
    float f = x - n;
    float p = 1.3333558146e-3f;
    p = fmaf(p, f, 9.6181291077e-3f);
    p = fmaf(p, f, 5.5504108665e-2f);
    p = fmaf(p, f, 2.4022650696e-1f);
    p = fmaf(p, f, 6.9314718056e-1f);
    p = fmaf(p, f, 1.0f);
    int e = __float_as_int(t) - 0x4B400000;
    return p * __int_as_float((e + 127) << 23);
}

// ============ fused prep: 6 weight transposes + x fp32->fp16 ================
__device__ __forceinline__ void transpose_tile32(const float* __restrict__ W,
                                                 __half* __restrict__ T,
                                                 int K, int N, int k0, int n0,
                                                 float* tile /* 32*33 */)
{
    const int tx = threadIdx.x & 31, ty = threadIdx.x >> 5;
    for (int i = ty; i < 32; i += 8)
        tile[i * 33 + tx] = W[(size_t)(k0 + i) * N + n0 + tx];
    __syncthreads();
    for (int i = ty; i < 32; i += 8)
        T[(size_t)(n0 + i) * K + k0 + tx] = __float2half(tile[tx * 33 + i]);
}

__global__ void prep_kernel(const float* __restrict__ Wq,
                            const float* __restrict__ Wk,
                            const float* __restrict__ Wv,
                            const float* __restrict__ Wo,
                            const float* __restrict__ W1,
                            const float* __restrict__ W2,
                            const float* __restrict__ x,
                            __half* __restrict__ wt,
                            __half* __restrict__ xh)
{
    __shared__ float tile[32 * 33];
    const int bid = blockIdx.x;
    if (bid < 1024) {
        const int z = bid >> 8, t = bid & 255;
        const float* W = (z == 0) ? Wq : (z == 1) ? Wk : (z == 2) ? Wv : Wo;
        transpose_tile32(W, wt + (size_t)z * 512 * 512, 512, 512,
                         (t >> 4) * 32, (t & 15) * 32, tile);
    } else if (bid < 2048) {
        const int t = bid - 1024;
        transpose_tile32(W1, wt + OFF_W1, 512, 2048,
                         (t >> 6) * 32, (t & 63) * 32, tile);
    } else if (bid < 3072) {
        const int t = bid - 2048;
        transpose_tile32(W2, wt + OFF_W2, 2048, 512,
                         (t >> 4) * 32, (t & 15) * 32, tile);
    } else {
        const int i = (bid - 3072) * 1024 + threadIdx.x * 4;
        float4 v = *(const float4*)(x + i);
        *(uint2*)(xh + i) = make_uint2(pack_f16x2(v.x, v.y), pack_f16x2(v.z, v.w));
    }
}

// ================ fp16 tensor-core GEMM: C = A @ B^T + bias =================
// A fp16 [M,K] row-major; B fp16 [N,K] K-major. fp32 accumulate.
// BK=64: 128-byte swizzled smem rows.
//   BN=128: 3-stage ring, one wait per chunk (warp grid 2x4, tile 64x32).
//   BN=64 : 4-stage ring, PAIRED chunks -> one wait per 2 chunks (4x2, 32x32).
// MODE 0: fp32 out (+bias +residual).  MODE 1: fp16 out (+bias, +relu).
// MODE 2: fused QKV (N=1536): fp16 out into q/k/v, per-section bias+scale.
#define ATILEB (128 * 128)        // A tile bytes per stage (16384)

template <int MODE, int BN>
__launch_bounds__(256, 2)
__global__ void sgemm_mma_kernel(const __half* __restrict__ A,
                                 const __half* __restrict__ B,
                                 const float* __restrict__ bias0,
                                 const float* __restrict__ bias1,
                                 const float* __restrict__ bias2,
                                 const float* __restrict__ Res,
                                 float* __restrict__ C,
                                 __half* __restrict__ Ch,
                                 __half* __restrict__ Qd,
                                 __half* __restrict__ Kd,
                                 __half* __restrict__ Vd,
                                 int M, int N, int K)
{
    constexpr int WM = (BN == 128) ? 2 : 4;    // warps along M
    constexpr int MI = 128 / (WM * 16);        // m16 tiles per warp
    constexpr int GSTAGE = (128 + BN) * 128;   // stage bytes

    extern __shared__ char smem[];
    const uint32_t sb = smem_u32(smem);
    const int tid = threadIdx.x;
    const int lane = tid & 31, wid = tid >> 5;
    const int wm = wid % WM, wn = wid / WM;
    const int bm = blockIdx.y * 128;
    const int bn = blockIdx.x * BN;

    const uint32_t rowA0 = (uint32_t)(wm * (MI * 16) + (lane & 15));
    const uint32_t cA    = (uint32_t)(lane >> 4);
    const uint32_t rowB0 = (uint32_t)(wn * 32 + ((lane & 16) ? 8 : 0) + (lane & 7));
    const uint32_t cB    = (uint32_t)((lane & 8) ? 1 : 0);
    const uint32_t l7    = (uint32_t)(lane & 7);

    const __half* aBase = A + (size_t)bm * K;
    const __half* bBase = B + (size_t)bn * K;

    const int nchunks = K >> 6;

    auto load_stage = [&](int s, int c) {
        const int k0 = c << 6;
        const uint32_t stg = sb + s * GSTAGE;
#pragma unroll
        for (int i = 0; i < (128 + BN) * 8 / 256; i++) {
            int idx = i * 256 + tid;
            if (idx < 1024) {                      // A: 128 rows x 8 chunks
                int r = idx >> 3, ch = idx & 7;
                cp_async16(stg + (uint32_t)r * 128 + (uint32_t)((ch ^ (r & 7)) << 4),
                           aBase + (size_t)r * K + k0 + ch * 8);
            } else {                               // B: BN rows x 8 chunks
                int rem = idx - 1024;
                int r = rem >> 3, ch = rem & 7;
                cp_async16(stg + ATILEB + (uint32_t)r * 128 + (uint32_t)((ch ^ (r & 7)) << 4),
                           bBase + (size_t)r * K + k0 + ch * 8);
            }
        }
    };

    float acc[MI][4][4];
#pragma unroll
    for (int i = 0; i < MI; i++)
#pragma unroll
        for (int j = 0; j < 4; j++)
#pragma unroll
            for (int t = 0; t < 4; t++) acc[i][j][t] = 0.f;

    auto compute_chunk = [&](uint32_t base) {
#pragma unroll
        for (int kst = 0; kst < 4; kst++) {
            const uint32_t swA = ((kst * 2 + cA) ^ l7) << 4;
            const uint32_t swB = ((kst * 2 + cB) ^ l7) << 4;
            uint32_t fa[MI][4], fb[2][4];
#pragma unroll
            for (int i = 0; i < MI; i++)
                ldm_x4(fa[i], base + (rowA0 + i * 16) * 128 + swA);
#pragma unroll
            for (int jj = 0; jj < 2; jj++)
                ldm_x4(fb[jj], base + ATILEB + (rowB0 + jj * 16) * 128 + swB);
#pragma unroll
            for (int i = 0; i < MI; i++)
#pragma unroll
                for (int j = 0; j < 4; j++)
                    mma_f16(acc[i][j], fa[i], &fb[j >> 1][(j & 1) * 2]);
        }
    };

    if (BN == 64) {
        // 4-stage ring, paired chunks (nchunks is a multiple of 4 here)
        load_stage(0, 0); CP_COMMIT();
        load_stage(1, 1); CP_COMMIT();
        load_stage(2, 2); CP_COMMIT();
        load_stage(3, 3); CP_COMMIT();

        for (int it = 0; it < nchunks / 2; it++) {
            const int kt = it * 2;
            CP_WAIT2();
            __syncthreads();
            compute_chunk(sb + (uint32_t)(kt & 3) * GSTAGE);
            compute_chunk(sb + (uint32_t)((kt + 1) & 3) * GSTAGE);
            __syncthreads();
            if (kt + 4 < nchunks) load_stage(kt & 3, kt + 4);
            CP_COMMIT();                       // unconditional: keeps accounting
            if (kt + 5 < nchunks) load_stage((kt + 1) & 3, kt + 5);
            CP_COMMIT();
        }
    } else {
        // 3-stage ring, one chunk per iteration
        load_stage(0, 0); CP_COMMIT();
        load_stage(1, 1); CP_COMMIT();

        int s = 0;
        for (int c = 0; c < nchunks; c++) {
            CP_WAIT1();
            __syncthreads();

            int sw = s + 2; if (sw >= 3) sw -= 3;
            if (c + 2 < nchunks) load_stage(sw, c + 2);
            CP_COMMIT();                       // unconditional

            compute_chunk(sb + (uint32_t)s * GSTAGE);
            if (++s == 3) s = 0;
        }
    }

    // -------- epilogue --------
    const int tr = lane >> 2;
    const int tc2 = (lane & 3) * 2;

    const float* biasS = bias0;
    __half* dstS = Qd;
    float scaleS = 1.f;
    if (MODE == 2) {
        const int sec = bn >> 9;
        biasS  = (sec == 0) ? bias0 : (sec == 1) ? bias1 : bias2;
        dstS   = (sec == 0) ? Qd : (sec == 1) ? Kd : Vd;
        scaleS = (sec == 0) ? SCALE_Q : 1.f;
    }

#pragma unroll
    for (int i = 0; i < MI; i++) {
#pragma unroll
        for (int j = 0; j < 4; j++) {
            const int r = bm + wm * (MI * 16) + i * 16 + tr;
            const int ncol = bn + wn * 32 + j * 8 + tc2;
#pragma unroll
            for (int half = 0; half < 2; half++) {
                float v0 = acc[i][j][half * 2 + 0];
                float v1 = acc[i][j][half * 2 + 1];
                const size_t row = (size_t)(r + half * 8);
                if (MODE == 0) {
                    float2 rv = *(const float2*)(Res + row * N + ncol);
                    v0 += bias0[ncol] + rv.x;
                    v1 += bias0[ncol + 1] + rv.y;
                    *(float2*)(C + row * N + ncol) = make_float2(v0, v1);
                } else if (MODE == 1) {
                    v0 = fmaxf(v0 + bias0[ncol], 0.f);
                    v1 = fmaxf(v1 + bias0[ncol + 1], 0.f);
                    *(uint32_t*)(Ch + row * N + ncol) = pack_f16x2(v0, v1);
                } else {
                    const int col = ncol & 511;
                    v0 = (v0 + biasS[col]) * scaleS;
                    v1 = (v1 + biasS[col + 1]) * scaleS;
                    *(uint32_t*)(dstS + row * 512 + col) = pack_f16x2(v0, v1);
                }
            }
        }
    }
}

// ================== tensor-core flash attention (fp16) ======================
// 128 q-rows per CTA, 8 warps (16 rows each), kv tiles of 64 tokens processed
// in pairs: 4 smem stages, one wait + one barrier pair per 2 tiles. Commits
// are UNCONDITIONAL (empty tail groups keep wait_group accounting exact).
#define ATT_KVOFF 24576
#define ATT_SMEM (8192 + 16384 + 4 * 16384)   // 90112

__launch_bounds__(256, 2)
__global__ void attn_mma_kernel(const __half* __restrict__ qh,
                                const __half* __restrict__ kh,
                                const __half* __restrict__ vh,
                                const int* __restrict__ mask,
                                __half* __restrict__ ctx)
{
    extern __shared__ char smc[];
    const uint32_t sb = smem_u32(smc);
    const int tid = threadIdx.x, lane = tid & 31, w = tid >> 5;
    const int qt = blockIdx.x, h = blockIdx.y, b = blockIdx.z;
    const int q0 = qt * 128;
    const size_t qbase  = ((size_t)(b * SEQ + q0)) * D_MODEL + h * DK;
    const size_t kvbase = ((size_t)(b * SEQ)) * D_MODEL + h * DK;

    float* madd = (float*)smc;
    for (int i = tid; i < SEQ; i += 256)
        madd[i] = (mask[b * SEQ + i] == 0) ? -1e9f : 0.f;

    auto load_kv = [&](int stg_i, int ktile) {
        const uint32_t stg = sb + ATT_KVOFF + stg_i * 16384;
        const size_t tokbase = kvbase + (size_t)ktile * 64 * D_MODEL;
        const __half* srcs[2] = { kh + tokbase, vh + tokbase };
#pragma unroll
        for (int i = 0; i < 4; i++) {
            int idx = i * 256 + tid;
            int t2 = idx >> 9;
            int rem = idx & 511;
            int r = rem >> 3, c = rem & 7;
            uint32_t off = (uint32_t)r * 128 + (uint32_t)((c ^ (r & 7)) << 4);
            cp_async16(stg + t2 * 8192 + off, srcs[t2] + (size_t)r * D_MODEL + c * 8);
        }
    };

    // prologue: Q (with kv0's group) + kv1..kv3
#pragma unroll
    for (int i = 0; i < 4; i++) {
        int idx = i * 256 + tid;
        int r = idx >> 3, c = idx & 7;
        uint32_t off = (uint32_t)r * 128 + (uint32_t)((c ^ (r & 7)) << 4);
        cp_async16(sb + 8192 + off, qh + qbase + (size_t)r * D_MODEL + c * 8);
    }
    load_kv(0, 0);
    CP_COMMIT();
    load_kv(1, 1);
    CP_COMMIT();
    load_kv(2, 2);
    CP_COMMIT();
    load_kv(3, 3);
    CP_COMMIT();

    CP_WAIT2();          // Q + kv0, kv1 complete
    __syncthreads();

    // Q fragments (registers for whole kernel)
    uint32_t qf[4][4];
    {
        const uint32_t qrow = (uint32_t)(w * 16 + (lane & 15));
        const uint32_t qc = (uint32_t)(lane >> 4);
#pragma unroll
        for (int ks = 0; ks < 4; ks++) {
            uint32_t c16 = ks * 2 + qc;
            uint32_t off = qrow * 128 + ((c16 ^ (qrow & 7)) << 4);
            ldm_x4(qf[ks], sb + 8192 + off);
        }
    }

    float m0 = -1e30f, m1 = -1e30f, l0 = 0.f, l1 = 0.f;
    float O[8][4];
#pragma unroll
    for (int g = 0; g < 8; g++)
#pragma unroll
        for (int t = 0; t < 4; t++) O[g][t] = 0.f;

    const uint32_t kr_base = (uint32_t)(((lane & 16) ? 8 : 0) + (lane & 7));
    const uint32_t kc_add  = (uint32_t)((lane & 8) ? 1 : 0);
    const uint32_t vr_base = (uint32_t)(lane & 15);
    const uint32_t vc_add  = (uint32_t)(lane >> 4);

    auto do_tile = [&](int kt, uint32_t stg) {
        float S[8][4];
#pragma unroll
        for (int g = 0; g < 8; g++)
#pragma unroll
            for (int t = 0; t < 4; t++) S[g][t] = 0.f;

#pragma unroll
        for (int tg = 0; tg < 4; tg++) {
            const uint32_t row = tg * 16 + kr_base;
#pragma unroll
            for (int ks = 0; ks < 4; ks++) {
                uint32_t c16 = ks * 2 + kc_add;
                uint32_t off = row * 128 + ((c16 ^ (row & 7)) << 4);
                uint32_t fh[4];
                ldm_x4(fh, stg + off);
                mma_f16(S[2 * tg],     qf[ks], &fh[0]);
                mma_f16(S[2 * tg + 1], qf[ks], &fh[2]);
            }
        }

        float mt0 = -1e30f, mt1 = -1e30f;
#pragma unroll
        for (int g = 0; g < 8; g++) {
            float2 ma = *(float2*)&madd[kt * 64 + g * 8 + (lane & 3) * 2];
            S[g][0] += ma.x; S[g][1] += ma.y;
            S[g][2] += ma.x; S[g][3] += ma.y;
            mt0 = fmaxf(mt0, fmaxf(S[g][0], S[g][1]));
            mt1 = fmaxf(mt1, fmaxf(S[g][2], S[g][3]));
        }
        mt0 = fmaxf(mt0, __shfl_xor_sync(0xffffffffu, mt0, 1));
        mt0 = fmaxf(mt0, __shfl_xor_sync(0xffffffffu, mt0, 2));
        mt1 = fmaxf(mt1, __shfl_xor_sync(0xffffffffu, mt1, 1));
        mt1 = fmaxf(mt1, __shfl_xor_sync(0xffffffffu, mt1, 2));

        if (__any_sync(0xffffffffu, (mt0 > m0) | (mt1 > m1))) {
            const float mn0 = fmaxf(m0, mt0), mn1 = fmaxf(m1, mt1);
            const float a0 = exp2p(m0 - mn0), a1 = exp2p(m1 - mn1);
            m0 = mn0; m1 = mn1;
            l0 *= a0; l1 *= a1;
#pragma unroll
            for (int g = 0; g < 8; g++) {
                O[g][0] *= a0; O[g][1] *= a0;
                O[g][2] *= a1; O[g][3] *= a1;
            }
        }

        float s0 = 0.f, s1 = 0.f;
        uint32_t ph[4][4];
#pragma unroll
        for (int g = 0; g < 8; g++) {
            uint32_t p01 = ex2_f16x2(pack_f16x2(S[g][0] - m0, S[g][1] - m0));
            uint32_t p23 = ex2_f16x2(pack_f16x2(S[g][2] - m1, S[g][3] - m1));
            float2 f01 = __half22float2(*(__half2*)&p01);
            float2 f23 = __half22float2(*(__half2*)&p23);
            s0 += f01.x + f01.y;
            s1 += f23.x + f23.y;
            ph[g >> 1][(g & 1) * 2 + 0] = p01;
            ph[g >> 1][(g & 1) * 2 + 1] = p23;
        }
        s0 += __shfl_xor_sync(0xffffffffu, s0, 1);
        s0 += __shfl_xor_sync(0xffffffffu, s0, 2);
        s1 += __shfl_xor_sync(0xffffffffu, s1, 1);
        s1 += __shfl_xor_sync(0xffffffffu, s1, 2);
        l0 += s0;
        l1 += s1;

#pragma unroll
        for (int gp = 0; gp < 4; gp++) {
#pragma unroll
            for (int j2 = 0; j2 < 4; j2++) {
                uint32_t row = j2 * 16 + vr_base;
                uint32_t c16 = gp * 2 + vc_add;
                uint32_t off = row * 128 + ((c16 ^ (row & 7)) << 4);
                uint32_t fh[4];
                ldm_x4_t(fh, stg + 8192 + off);
                mma_f16(O[2 * gp],     ph[j2], &fh[0]);
                mma_f16(O[2 * gp + 1], ph[j2], &fh[2]);
            }
        }
    };

    // mainloop: 2 tiles per iteration, 4-stage ring, one wait + one sync pair
    for (int it = 0; it < SEQ / 128; it++) {
        const int kt = it * 2;
        if (it > 0) { CP_WAIT2(); __syncthreads(); }
        const int sA = kt & 3, sB = (kt + 1) & 3;

        do_tile(kt,     sb + ATT_KVOFF + sA * 16384);
        do_tile(kt + 1, sb + ATT_KVOFF + sB * 16384);

        __syncthreads();
        if (kt + 4 < SEQ / 64) load_kv(sA, kt + 4);
        CP_COMMIT();                          // unconditional: exact accounting
        if (kt + 5 < SEQ / 64) load_kv(sB, kt + 5);
        CP_COMMIT();
    }

    // ---- epilogue: normalize + fp16 store ----
    const float inv0 = 1.f / l0, inv1 = 1.f / l1;
    const int rg = q0 + w * 16 + (lane >> 2);
    const size_t ob = ((size_t)(b * SEQ)) * D_MODEL + h * DK;
#pragma unroll
    for (int g = 0; g < 8; g++) {
        const int col = g * 8 + (lane & 3) * 2;
        *(uint32_t*)(ctx + ob + (size_t)rg * D_MODEL + col) =
            pack_f16x2(O[g][0] * inv0, O[g][1] * inv0);
        *(uint32_t*)(ctx + ob + (size_t)(rg + 8) * D_MODEL + col) =
            pack_f16x2(O[g][2] * inv1, O[g][3] * inv1);
    }
}

// -------- LayerNorm over precomputed sum buffer (optional fp16 copy) -------
template <bool H16>
__launch_bounds__(128)
__global__ void ln_kernel(const float* __restrict__ a,
                          const float* __restrict__ g,
                          const float* __restrict__ beta,
                          float* __restrict__ out,
                          __half* __restrict__ oh)
{
    const int row = blockIdx.x;
    const int tid = threadIdx.x;
    const size_t off = (size_t)row * D_MODEL;
    float v[4];
    float s = 0.f, ss = 0.f;
#pragma unroll
    for (int i = 0; i < 4; i++) {
        int c = tid + i * 128;
        float x = a[off + c];
        v[i] = x; s += x; ss += x * x;
    }
#pragma unroll
    for (int o = 16; o > 0; o >>= 1) {
        s  += __shfl_xor_sync(0xffffffffu, s, o);
        ss += __shfl_xor_sync(0xffffffffu, ss, o);
    }
    __shared__ float rs[4], rss[4];
    int w = tid >> 5, lane = tid & 31;
    if (lane == 0) { rs[w] = s; rss[w] = ss; }
    __syncthreads();
    s  = rs[0]  + rs[1]  + rs[2]  + rs[3];
    ss = rss[0] + rss[1] + rss[2] + rss[3];
    float mu   = s * (1.f / D_MODEL);
    float var  = ss * (1.f / D_MODEL) - mu * mu;
    float rstd = rsqrtf(var + 1e-5f);
#pragma unroll
    for (int i = 0; i < 4; i++) {
        int c = tid + i * 128;
        float y = (v[i] - mu) * rstd * g[c] + beta[c];
        out[off + c] = y;
        if (H16) oh[off + c] = __float2half(y);
    }
}

// ---------------- launch ---------------------------------------------------
extern "C" void kernel_launch(void* const* d_in, const int* in_sizes, int n_in,
                              void* d_out, int out_size)
{
    (void)in_sizes; (void)n_in; (void)out_size;
    const float* x    = (const float*)d_in[0];
    const int*   mask = (const int*)  d_in[1];
    const float* Wq = (const float*)d_in[2];
    const float* bq = (const float*)d_in[3];
    const float* Wk = (const float*)d_in[4];
    const float* bk = (const float*)d_in[5];
    const float* Wv = (const float*)d_in[6];
    const float* bv = (const float*)d_in[7];
    const float* Wo = (const float*)d_in[8];
    const float* bo = (const float*)d_in[9];
    const float* W1 = (const float*)d_in[10];
    const float* b1 = (const float*)d_in[11];
    const float* W2 = (const float*)d_in[12];
    const float* b2 = (const float*)d_in[13];
    const float* g1 = (const float*)d_in[14];
    const float* be1= (const float*)d_in[15];
    const float* g2 = (const float*)d_in[16];
    const float* be2= (const float*)d_in[17];
    float* out = (float*)d_out;

    float *x1, *tmp;
    __half *wt, *xh, *qh, *kh, *vh, *ctx, *x1h, *ffh;
    cudaGetSymbolAddress((void**)&x1,  g_x1);
    cudaGetSymbolAddress((void**)&tmp, g_tmp);
    cudaGetSymbolAddress((void**)&wt,  g_wt);
    cudaGetSymbolAddress((void**)&xh,  g_xh);
    cudaGetSymbolAddress((void**)&qh,  g_qh);
    cudaGetSymbolAddress((void**)&kh,  g_kh);
    cudaGetSymbolAddress((void**)&vh,  g_vh);
    cudaGetSymbolAddress((void**)&ctx, g_ctx);
    cudaGetSymbolAddress((void**)&x1h, g_x1h);
    cudaGetSymbolAddress((void**)&ffh, g_ffh);

    const int SM128 = 3 * (128 + 128) * 128;   // 98304 (3 stages)
    const int SM64  = 4 * (128 + 64) * 128;    // 98304 (4 stages)
    cudaFuncSetAttribute((const void*)sgemm_mma_kernel<0, 64>,
                         cudaFuncAttributeMaxDynamicSharedMemorySize, SM64);
    cudaFuncSetAttribute((const void*)sgemm_mma_kernel<1, 128>,
                         cudaFuncAttributeMaxDynamicSharedMemorySize, SM128);
    cudaFuncSetAttribute((const void*)sgemm_mma_kernel<2, 128>,
                         cudaFuncAttributeMaxDynamicSharedMemorySize, SM128);
    cudaFuncSetAttribute(attn_mma_kernel,
                         cudaFuncAttributeMaxDynamicSharedMemorySize, ATT_SMEM);

    const int M = NTOK;

    // fused prep: all weight transposes + x convert (one launch)
    prep_kernel<<<5120, 256>>>(Wq, Wk, Wv, Wo, W1, W2, x, wt, xh);

    // fused QKV projection (fp16 out, Q pre-scaled) — BN=128 (best measured)
    {
        dim3 grid(1536 / 128, M / 128);
        sgemm_mma_kernel<2, 128><<<grid, 256, SM128>>>(
            xh, wt + OFF_WQKV, bq, bk, bv, nullptr,
            nullptr, nullptr, qh, kh, vh, M, 1536, 512);
    }

    // flash attention (fp16 tensor cores, paired KV tiles)
    {
        dim3 grid(SEQ / 128, N_HEADS, BATCH);
        attn_mma_kernel<<<grid, 256, ATT_SMEM>>>(qh, kh, vh, mask, ctx);
    }

    // Wo projection (+bias +residual x) -> tmp; x1 = LN(tmp)
    {
        dim3 grid(512 / 64, M / 128);
        sgemm_mma_kernel<0, 64><<<grid, 256, SM64>>>(
            ctx, wt + OFF_WO, bo, nullptr, nullptr, x,
            tmp, nullptr, nullptr, nullptr, nullptr, M, 512, 512);
        ln_kernel<true><<<M, 128>>>(tmp, g1, be1, x1, x1h);
    }

    // FF
    {
        dim3 grid1(2048 / 128, M / 128);
        sgemm_mma_kernel<1, 128><<<grid1, 256, SM128>>>(
            x1h, wt + OFF_W1, b1, nullptr, nullptr, nullptr,
            nullptr, ffh, nullptr, nullptr, nullptr, M, 2048, 512);
        dim3 grid2(512 / 64, M / 128);
        sgemm_mma_kernel<0, 64><<<grid2, 256, SM64>>>(
            ffh, wt + OFF_W2, b2, nullptr, nullptr, x1,
            tmp, nullptr, nullptr, nullptr, nullptr, M, 512, 2048);
        ln_kernel<false><<<M, 128>>>(tmp, g2, be2, out, nullptr);
    }
}

// round 16
// speedup vs baseline: 1.0151x; 1.0151x over previous
#include <cuda_runtime.h>
#include <cuda_fp16.h>
#include <cstdint>
#include <math.h>

#define D_MODEL 512
#define N_HEADS 8
#define DK      64
#define D_FF    2048
#define BATCH   2
#define SEQ     2048
#define NTOK    (BATCH * SEQ)   // 4096

#define SCALE_Q 0.18033688011112042f   // 0.125 * log2(e)

// ---------------- scratch (device globals; no allocation allowed) ----------
static __device__ __half g_tmp[(size_t)NTOK * D_MODEL];   // fp16 glue buffer

static __device__ __half g_xh [(size_t)NTOK * D_MODEL];
static __device__ __half g_qh [(size_t)NTOK * D_MODEL];
static __device__ __half g_kh [(size_t)NTOK * D_MODEL];
static __device__ __half g_vh [(size_t)NTOK * D_MODEL];
static __device__ __half g_ctx[(size_t)NTOK * D_MODEL];
static __device__ __half g_x1h[(size_t)NTOK * D_MODEL];
static __device__ __half g_ffh[(size_t)NTOK * D_FF];

// transposed fp16 weights: Wt[n][k]; WQ/WK/WV contiguous -> fused [1536,512]
#define OFF_WQKV 0
#define OFF_WO   (3*512*512)
#define OFF_W1   (4*512*512)
#define OFF_W2   (4*512*512 + 2048*512)
#define WT_TOTAL (4*512*512 + 2*2048*512)
static __device__ __half g_wt[WT_TOTAL];

// ======================= PTX helpers (base sm_80+ features) ================
__device__ __forceinline__ uint32_t smem_u32(const void* p) {
    uint32_t a;
    asm("{ .reg .u64 t; cvta.to.shared.u64 t, %1; cvt.u32.u64 %0, t; }"
        : "=r"(a) : "l"(p));
    return a;
}
__device__ __forceinline__ void cp_async16(uint32_t dst, const void* src) {
    asm volatile("cp.async.cg.shared.global [%0], [%1], 16;" :: "r"(dst), "l"(src));
}
#define CP_COMMIT() asm volatile("cp.async.commit_group;" ::: "memory")
#define CP_WAIT1()  asm volatile("cp.async.wait_group 1;" ::: "memory")
#define CP_WAIT2()  asm volatile("cp.async.wait_group 2;" ::: "memory")

__device__ __forceinline__ void ldm_x4(uint32_t* r, uint32_t addr) {
    asm volatile("ldmatrix.sync.aligned.m8n8.x4.shared.b16 {%0,%1,%2,%3}, [%4];"
        : "=r"(r[0]), "=r"(r[1]), "=r"(r[2]), "=r"(r[3]) : "r"(addr));
}
__device__ __forceinline__ void ldm_x4_t(uint32_t* r, uint32_t addr) {
    asm volatile("ldmatrix.sync.aligned.m8n8.x4.trans.shared.b16 {%0,%1,%2,%3}, [%4];"
        : "=r"(r[0]), "=r"(r[1]), "=r"(r[2]), "=r"(r[3]) : "r"(addr));
}
__device__ __forceinline__ void mma_f16(float* c, const uint32_t* a, const uint32_t* b) {
    asm volatile("mma.sync.aligned.m16n8k16.row.col.f32.f16.f16.f32 "
        "{%0,%1,%2,%3}, {%4,%5,%6,%7}, {%8,%9}, {%0,%1,%2,%3};"
        : "+f"(c[0]), "+f"(c[1]), "+f"(c[2]), "+f"(c[3])
        : "r"(a[0]), "r"(a[1]), "r"(a[2]), "r"(a[3]), "r"(b[0]), "r"(b[1]));
}
// pack (lo, hi) -> f16x2 (lo in low half)
__device__ __forceinline__ uint32_t pack_f16x2(float lo, float hi) {
    uint32_t r;
    asm("cvt.rn.f16x2.f32 %0, %1, %2;" : "=r"(r) : "f"(hi), "f"(lo));
    return r;
}
// packed fp16x2 exp2 on MUFU (sm_75+)
__device__ __forceinline__ uint32_t ex2_f16x2(uint32_t x) {
    uint32_t r;
    asm("ex2.approx.f16x2 %0, %1;" : "=r"(r) : "r"(x));
    return r;
}

// fast exp2 for x <= 0 on the FMA pipe (no MUFU). abs err ~2e-6.
__device__ __forceinline__ float exp2p(float x) {
    x = fmaxf(x, -126.f);
    float t = __fadd_rn(x, 12582912.f);
    float n = __fadd_rn(t, -12582912.f);
    float f = x - n;
    float p = 1.3333558146e-3f;
    p = fmaf(p, f, 9.6181291077e-3f);
    p = fmaf(p, f, 5.5504108665e-2f);
    p = fmaf(p, f, 2.4022650696e-1f);
    p = fmaf(p, f, 6.9314718056e-1f);
    p = fmaf(p, f, 1.0f);
    int e = __float_as_int(t) - 0x4B400000;
    return p * __int_as_float((e + 127) << 23);
}

// ============ fused prep: 6 weight transposes + x fp32->fp16 ================
__device__ __forceinline__ void transpose_tile32(const float* __restrict__ W,
                                                 __half* __restrict__ T,
                                                 int K, int N, int k0, int n0,
                                                 float* tile /* 32*33 */)
{
    const int tx = threadIdx.x & 31, ty = threadIdx.x >> 5;
    for (int i = ty; i < 32; i += 8)
        tile[i * 33 + tx] = W[(size_t)(k0 + i) * N + n0 + tx];
    __syncthreads();
    for (int i = ty; i < 32; i += 8)
        T[(size_t)(n0 + i) * K + k0 + tx] = __float2half(tile[tx * 33 + i]);
}

__global__ void prep_kernel(const float* __restrict__ Wq,
                            const float* __restrict__ Wk,
                            const float* __restrict__ Wv,
                            const float* __restrict__ Wo,
                            const float* __restrict__ W1,
                            const float* __restrict__ W2,
                            const float* __restrict__ x,
                            __half* __restrict__ wt,
                            __half* __restrict__ xh)
{
    __shared__ float tile[32 * 33];
    const int bid = blockIdx.x;
    if (bid < 1024) {
        const int z = bid >> 8, t = bid & 255;
        const float* W = (z == 0) ? Wq : (z == 1) ? Wk : (z == 2) ? Wv : Wo;
        transpose_tile32(W, wt + (size_t)z * 512 * 512, 512, 512,
                         (t >> 4) * 32, (t & 15) * 32, tile);
    } else if (bid < 2048) {
        const int t = bid - 1024;
        transpose_tile32(W1, wt + OFF_W1, 512, 2048,
                         (t >> 6) * 32, (t & 63) * 32, tile);
    } else if (bid < 3072) {
        const int t = bid - 2048;
        transpose_tile32(W2, wt + OFF_W2, 2048, 512,
                         (t >> 4) * 32, (t & 15) * 32, tile);
    } else {
        const int i = (bid - 3072) * 1024 + threadIdx.x * 4;
        float4 v = *(const float4*)(x + i);
        *(uint2*)(xh + i) = make_uint2(pack_f16x2(v.x, v.y), pack_f16x2(v.z, v.w));
    }
}

// ================ fp16 tensor-core GEMM: C = A @ B^T + bias =================
// A fp16 [M,K] row-major; B fp16 [N,K] K-major. fp32 accumulate.
// BK=64, 128-byte swizzled smem rows.
//   BN=128: 3-stage ring (warp grid 2x4, tile 64x32).
//   BN=64 : 4-stage ring, paired chunks, one wait per 2 chunks (4x2, 32x32).
// MODE 0: fp16 out (+bias + fp32 residual)   [Wo]
// MODE 1: fp16 out (+bias, +relu)            [FF1]
// MODE 2: fused QKV (N=1536), per-section bias+scale
// MODE 3: fp16 out (+bias + fp16 residual)   [FF2]
#define ATILEB (128 * 128)        // A tile bytes per stage (16384)

template <int MODE, int BN>
__launch_bounds__(256, 2)
__global__ void sgemm_mma_kernel(const __half* __restrict__ A,
                                 const __half* __restrict__ B,
                                 const float* __restrict__ bias0,
                                 const float* __restrict__ bias1,
                                 const float* __restrict__ bias2,
                                 const float* __restrict__ Res,
                                 const __half* __restrict__ ResH,
                                 __half* __restrict__ Ch,
                                 __half* __restrict__ Qd,
                                 __half* __restrict__ Kd,
                                 __half* __restrict__ Vd,
                                 int M, int N, int K)
{
    constexpr int WM = (BN == 128) ? 2 : 4;    // warps along M
    constexpr int MI = 128 / (WM * 16);        // m16 tiles per warp
    constexpr int GSTAGE = (128 + BN) * 128;   // stage bytes

    extern __shared__ char smem[];
    const uint32_t sb = smem_u32(smem);
    const int tid = threadIdx.x;
    const int lane = tid & 31, wid = tid >> 5;
    const int wm = wid % WM, wn = wid / WM;
    const int bm = blockIdx.y * 128;
    const int bn = blockIdx.x * BN;

    const uint32_t rowA0 = (uint32_t)(wm * (MI * 16) + (lane & 15));
    const uint32_t cA    = (uint32_t)(lane >> 4);
    const uint32_t rowB0 = (uint32_t)(wn * 32 + ((lane & 16) ? 8 : 0) + (lane & 7));
    const uint32_t cB    = (uint32_t)((lane & 8) ? 1 : 0);
    const uint32_t l7    = (uint32_t)(lane & 7);

    const __half* aBase = A + (size_t)bm * K;
    const __half* bBase = B + (size_t)bn * K;

    const int nchunks = K >> 6;

    auto load_stage = [&](int s, int c) {
        const int k0 = c << 6;
        const uint32_t stg = sb + s * GSTAGE;
#pragma unroll
        for (int i = 0; i < (128 + BN) * 8 / 256; i++) {
            int idx = i * 256 + tid;
            if (idx < 1024) {                      // A: 128 rows x 8 chunks
                int r = idx >> 3, ch = idx & 7;
                cp_async16(stg + (uint32_t)r * 128 + (uint32_t)((ch ^ (r & 7)) << 4),
                           aBase + (size_t)r * K + k0 + ch * 8);
            } else {                               // B: BN rows x 8 chunks
                int rem = idx - 1024;
                int r = rem >> 3, ch = rem & 7;
                cp_async16(stg + ATILEB + (uint32_t)r * 128 + (uint32_t)((ch ^ (r & 7)) << 4),
                           bBase + (size_t)r * K + k0 + ch * 8);
            }
        }
    };

    float acc[MI][4][4];
#pragma unroll
    for (int i = 0; i < MI; i++)
#pragma unroll
        for (int j = 0; j < 4; j++)
#pragma unroll
            for (int t = 0; t < 4; t++) acc[i][j][t] = 0.f;

    auto compute_chunk = [&](uint32_t base) {
#pragma unroll
        for (int kst = 0; kst < 4; kst++) {
            const uint32_t swA = ((kst * 2 + cA) ^ l7) << 4;
            const uint32_t swB = ((kst * 2 + cB) ^ l7) << 4;
            uint32_t fa[MI][4], fb[2][4];
#pragma unroll
            for (int i = 0; i < MI; i++)
                ldm_x4(fa[i], base + (rowA0 + i * 16) * 128 + swA);
#pragma unroll
            for (int jj = 0; jj < 2; jj++)
                ldm_x4(fb[jj], base + ATILEB + (rowB0 + jj * 16) * 128 + swB);
#pragma unroll
            for (int i = 0; i < MI; i++)
#pragma unroll
                for (int j = 0; j < 4; j++)
                    mma_f16(acc[i][j], fa[i], &fb[j >> 1][(j & 1) * 2]);
        }
    };

    if (BN == 64) {
        // 4-stage ring, paired chunks (nchunks is a multiple of 4 here)
        load_stage(0, 0); CP_COMMIT();
        load_stage(1, 1); CP_COMMIT();
        load_stage(2, 2); CP_COMMIT();
        load_stage(3, 3); CP_COMMIT();

        for (int it = 0; it < nchunks / 2; it++) {
            const int kt = it * 2;
            CP_WAIT2();
            __syncthreads();
            compute_chunk(sb + (uint32_t)(kt & 3) * GSTAGE);
            compute_chunk(sb + (uint32_t)((kt + 1) & 3) * GSTAGE);
            __syncthreads();
            if (kt + 4 < nchunks) load_stage(kt & 3, kt + 4);
            CP_COMMIT();                       // unconditional: keeps accounting
            if (kt + 5 < nchunks) load_stage((kt + 1) & 3, kt + 5);
            CP_COMMIT();
        }
    } else {
        // 3-stage ring, one chunk per iteration
        load_stage(0, 0); CP_COMMIT();
        load_stage(1, 1); CP_COMMIT();

        int s = 0;
        for (int c = 0; c < nchunks; c++) {
            CP_WAIT1();
            __syncthreads();

            int sw = s + 2; if (sw >= 3) sw -= 3;
            if (c + 2 < nchunks) load_stage(sw, c + 2);
            CP_COMMIT();                       // unconditional

            compute_chunk(sb + (uint32_t)s * GSTAGE);
            if (++s == 3) s = 0;
        }
    }

    // -------- epilogue --------
    const int tr = lane >> 2;
    const int tc2 = (lane & 3) * 2;

    const float* biasS = bias0;
    __half* dstS = Qd;
    float scaleS = 1.f;
    if (MODE == 2) {
        const int sec = bn >> 9;
        biasS  = (sec == 0) ? bias0 : (sec == 1) ? bias1 : bias2;
        dstS   = (sec == 0) ? Qd : (sec == 1) ? Kd : Vd;
        scaleS = (sec == 0) ? SCALE_Q : 1.f;
    }

#pragma unroll
    for (int i = 0; i < MI; i++) {
#pragma unroll
        for (int j = 0; j < 4; j++) {
            const int r = bm + wm * (MI * 16) + i * 16 + tr;
            const int ncol = bn + wn * 32 + j * 8 + tc2;
#pragma unroll
            for (int half = 0; half < 2; half++) {
                float v0 = acc[i][j][half * 2 + 0];
                float v1 = acc[i][j][half * 2 + 1];
                const size_t row = (size_t)(r + half * 8);
                if (MODE == 0 || MODE == 3) {
                    float r0, r1;
                    if (MODE == 0) {
                        float2 rv = *(const float2*)(Res + row * N + ncol);
                        r0 = rv.x; r1 = rv.y;
                    } else {
                        __half2 rh = *(const __half2*)(ResH + row * N + ncol);
                        float2 rv = __half22float2(rh);
                        r0 = rv.x; r1 = rv.y;
                    }
                    v0 += bias0[ncol] + r0;
                    v1 += bias0[ncol + 1] + r1;
                    *(uint32_t*)(Ch + row * N + ncol) = pack_f16x2(v0, v1);
                } else if (MODE == 1) {
                    v0 = fmaxf(v0 + bias0[ncol], 0.f);
                    v1 = fmaxf(v1 + bias0[ncol + 1], 0.f);
                    *(uint32_t*)(Ch + row * N + ncol) = pack_f16x2(v0, v1);
                } else {
                    const int col = ncol & 511;
                    v0 = (v0 + biasS[col]) * scaleS;
                    v1 = (v1 + biasS[col + 1]) * scaleS;
                    *(uint32_t*)(dstS + row * 512 + col) = pack_f16x2(v0, v1);
                }
            }
        }
    }
}

// ================== tensor-core flash attention (fp16) ======================
// 128 q-rows per CTA, 8 warps (16 rows each), kv tiles of 64 tokens processed
// in pairs: 4 smem stages, one wait + one barrier pair per 2 tiles. Commits
// are UNCONDITIONAL (empty tail groups keep wait_group accounting exact).
#define ATT_KVOFF 24576
#define ATT_SMEM (8192 + 16384 + 4 * 16384)   // 90112

__launch_bounds__(256, 2)
__global__ void attn_mma_kernel(const __half* __restrict__ qh,
                                const __half* __restrict__ kh,
                                const __half* __restrict__ vh,
                                const int* __restrict__ mask,
                                __half* __restrict__ ctx)
{
    extern __shared__ char smc[];
    const uint32_t sb = smem_u32(smc);
    const int tid = threadIdx.x, lane = tid & 31, w = tid >> 5;
    const int qt = blockIdx.x, h = blockIdx.y, b = blockIdx.z;
    const int q0 = qt * 128;
    const size_t qbase  = ((size_t)(b * SEQ + q0)) * D_MODEL + h * DK;
    const size_t kvbase = ((size_t)(b * SEQ)) * D_MODEL + h * DK;

    float* madd = (float*)smc;
    for (int i = tid; i < SEQ; i += 256)
        madd[i] = (mask[b * SEQ + i] == 0) ? -1e9f : 0.f;

    auto load_kv = [&](int stg_i, int ktile) {
        const uint32_t stg = sb + ATT_KVOFF + stg_i * 16384;
        const size_t tokbase = kvbase + (size_t)ktile * 64 * D_MODEL;
        const __half* srcs[2] = { kh + tokbase, vh + tokbase };
#pragma unroll
        for (int i = 0; i < 4; i++) {
            int idx = i * 256 + tid;
            int t2 = idx >> 9;
            int rem = idx & 511;
            int r = rem >> 3, c = rem & 7;
            uint32_t off = (uint32_t)r * 128 + (uint32_t)((c ^ (r & 7)) << 4);
            cp_async16(stg + t2 * 8192 + off, srcs[t2] + (size_t)r * D_MODEL + c * 8);
        }
    };

    // prologue: Q (with kv0's group) + kv1..kv3
#pragma unroll
    for (int i = 0; i < 4; i++) {
        int idx = i * 256 + tid;
        int r = idx >> 3, c = idx & 7;
        uint32_t off = (uint32_t)r * 128 + (uint32_t)((c ^ (r & 7)) << 4);
        cp_async16(sb + 8192 + off, qh + qbase + (size_t)r * D_MODEL + c * 8);
    }
    load_kv(0, 0);
    CP_COMMIT();
    load_kv(1, 1);
    CP_COMMIT();
    load_kv(2, 2);
    CP_COMMIT();
    load_kv(3, 3);
    CP_COMMIT();

    CP_WAIT2();          // Q + kv0, kv1 complete
    __syncthreads();

    // Q fragments (registers for whole kernel)
    uint32_t qf[4][4];
    {
        const uint32_t qrow = (uint32_t)(w * 16 + (lane & 15));
        const uint32_t qc = (uint32_t)(lane >> 4);
#pragma unroll
        for (int ks = 0; ks < 4; ks++) {
            uint32_t c16 = ks * 2 + qc;
            uint32_t off = qrow * 128 + ((c16 ^ (qrow & 7)) << 4);
            ldm_x4(qf[ks], sb + 8192 + off);
        }
    }

    float m0 = -1e30f, m1 = -1e30f, l0 = 0.f, l1 = 0.f;
    float O[8][4];
#pragma unroll
    for (int g = 0; g < 8; g++)
#pragma unroll
        for (int t = 0; t < 4; t++) O[g][t] = 0.f;

    const uint32_t kr_base = (uint32_t)(((lane & 16) ? 8 : 0) + (lane & 7));
    const uint32_t kc_add  = (uint32_t)((lane & 8) ? 1 : 0);
    const uint32_t vr_base = (uint32_t)(lane & 15);
    const uint32_t vc_add  = (uint32_t)(lane >> 4);

    auto do_tile = [&](int kt, uint32_t stg) {
        float S[8][4];
#pragma unroll
        for (int g = 0; g < 8; g++)
#pragma unroll
            for (int t = 0; t < 4; t++) S[g][t] = 0.f;

#pragma unroll
        for (int tg = 0; tg < 4; tg++) {
            const uint32_t row = tg * 16 + kr_base;
#pragma unroll
            for (int ks = 0; ks < 4; ks++) {
                uint32_t c16 = ks * 2 + kc_add;
                uint32_t off = row * 128 + ((c16 ^ (row & 7)) << 4);
                uint32_t fh[4];
                ldm_x4(fh, stg + off);
                mma_f16(S[2 * tg],     qf[ks], &fh[0]);
                mma_f16(S[2 * tg + 1], qf[ks], &fh[2]);
            }
        }

        float mt0 = -1e30f, mt1 = -1e30f;
#pragma unroll
        for (int g = 0; g < 8; g++) {
            float2 ma = *(float2*)&madd[kt * 64 + g * 8 + (lane & 3) * 2];
            S[g][0] += ma.x; S[g][1] += ma.y;
            S[g][2] += ma.x; S[g][3] += ma.y;
            mt0 = fmaxf(mt0, fmaxf(S[g][0], S[g][1]));
            mt1 = fmaxf(mt1, fmaxf(S[g][2], S[g][3]));
        }
        mt0 = fmaxf(mt0, __shfl_xor_sync(0xffffffffu, mt0, 1));
        mt0 = fmaxf(mt0, __shfl_xor_sync(0xffffffffu, mt0, 2));
        mt1 = fmaxf(mt1, __shfl_xor_sync(0xffffffffu, mt1, 1));
        mt1 = fmaxf(mt1, __shfl_xor_sync(0xffffffffu, mt1, 2));

        if (__any_sync(0xffffffffu, (mt0 > m0) | (mt1 > m1))) {
            const float mn0 = fmaxf(m0, mt0), mn1 = fmaxf(m1, mt1);
            const float a0 = exp2p(m0 - mn0), a1 = exp2p(m1 - mn1);
            m0 = mn0; m1 = mn1;
            l0 *= a0; l1 *= a1;
#pragma unroll
            for (int g = 0; g < 8; g++) {
                O[g][0] *= a0; O[g][1] *= a0;
                O[g][2] *= a1; O[g][3] *= a1;
            }
        }

        float s0 = 0.f, s1 = 0.f;
        uint32_t ph[4][4];
#pragma unroll
        for (int g = 0; g < 8; g++) {
            uint32_t p01 = ex2_f16x2(pack_f16x2(S[g][0] - m0, S[g][1] - m0));
            uint32_t p23 = ex2_f16x2(pack_f16x2(S[g][2] - m1, S[g][3] - m1));
            float2 f01 = __half22float2(*(__half2*)&p01);
            float2 f23 = __half22float2(*(__half2*)&p23);
            s0 += f01.x + f01.y;
            s1 += f23.x + f23.y;
            ph[g >> 1][(g & 1) * 2 + 0] = p01;
            ph[g >> 1][(g & 1) * 2 + 1] = p23;
        }
        s0 += __shfl_xor_sync(0xffffffffu, s0, 1);
        s0 += __shfl_xor_sync(0xffffffffu, s0, 2);
        s1 += __shfl_xor_sync(0xffffffffu, s1, 1);
        s1 += __shfl_xor_sync(0xffffffffu, s1, 2);
        l0 += s0;
        l1 += s1;

#pragma unroll
        for (int gp = 0; gp < 4; gp++) {
#pragma unroll
            for (int j2 = 0; j2 < 4; j2++) {
                uint32_t row = j2 * 16 + vr_base;
                uint32_t c16 = gp * 2 + vc_add;
                uint32_t off = row * 128 + ((c16 ^ (row & 7)) << 4);
                uint32_t fh[4];
                ldm_x4_t(fh, stg + 8192 + off);
                mma_f16(O[2 * gp],     ph[j2], &fh[0]);
                mma_f16(O[2 * gp + 1], ph[j2], &fh[2]);
            }
        }
    };

    // mainloop: 2 tiles per iteration, 4-stage ring, one wait + one sync pair
    for (int it = 0; it < SEQ / 128; it++) {
        const int kt = it * 2;
        if (it > 0) { CP_WAIT2(); __syncthreads(); }
        const int sA = kt & 3, sB = (kt + 1) & 3;

        do_tile(kt,     sb + ATT_KVOFF + sA * 16384);
        do_tile(kt + 1, sb + ATT_KVOFF + sB * 16384);

        __syncthreads();
        if (kt + 4 < SEQ / 64) load_kv(sA, kt + 4);
        CP_COMMIT();                          // unconditional: exact accounting
        if (kt + 5 < SEQ / 64) load_kv(sB, kt + 5);
        CP_COMMIT();
    }

    // ---- epilogue: normalize + fp16 store ----
    const float inv0 = 1.f / l0, inv1 = 1.f / l1;
    const int rg = q0 + w * 16 + (lane >> 2);
    const size_t ob = ((size_t)(b * SEQ)) * D_MODEL + h * DK;
#pragma unroll
    for (int g = 0; g < 8; g++) {
        const int col = g * 8 + (lane & 3) * 2;
        *(uint32_t*)(ctx + ob + (size_t)rg * D_MODEL + col) =
            pack_f16x2(O[g][0] * inv0, O[g][1] * inv0);
        *(uint32_t*)(ctx + ob + (size_t)(rg + 8) * D_MODEL + col) =
            pack_f16x2(O[g][2] * inv1, O[g][3] * inv1);
    }
}

// -------- LayerNorm over fp16 sum buffer --------
// H16OUT: write fp16 (feeds next GEMM). else: write fp32 (final output).
template <bool H16OUT>
__launch_bounds__(128)
__global__ void ln_kernel(const __half* __restrict__ a,
                          const float* __restrict__ g,
                          const float* __restrict__ beta,
                          float* __restrict__ out,
                          __half* __restrict__ oh)
{
    const int row = blockIdx.x;
    const int tid = threadIdx.x;
    const size_t off = (size_t)row * D_MODEL;
    const int c0 = tid * 4;

    uint2 raw = *(const uint2*)(a + off + c0);
    float2 f01 = __half22float2(*(__half2*)&raw.x);
    float2 f23 = __half22float2(*(__half2*)&raw.y);
    float v[4] = { f01.x, f01.y, f23.x, f23.y };

    float s = v[0] + v[1] + v[2] + v[3];
    float ss = v[0] * v[0] + v[1] * v[1] + v[2] * v[2] + v[3] * v[3];
#pragma unroll
    for (int o = 16; o > 0; o >>= 1) {
        s  += __shfl_xor_sync(0xffffffffu, s, o);
        ss += __shfl_xor_sync(0xffffffffu, ss, o);
    }
    __shared__ float rs[4], rss[4];
    int w = tid >> 5, lane = tid & 31;
    if (lane == 0) { rs[w] = s; rss[w] = ss; }
    __syncthreads();
    s  = rs[0]  + rs[1]  + rs[2]  + rs[3];
    ss = rss[0] + rss[1] + rss[2] + rss[3];
    float mu   = s * (1.f / D_MODEL);
    float var  = ss * (1.f / D_MODEL) - mu * mu;
    float rstd = rsqrtf(var + 1e-5f);

    float y[4];
#pragma unroll
    for (int i = 0; i < 4; i++)
        y[i] = (v[i] - mu) * rstd * g[c0 + i] + beta[c0 + i];

    if (H16OUT) {
        *(uint2*)(oh + off + c0) =
            make_uint2(pack_f16x2(y[0], y[1]), pack_f16x2(y[2], y[3]));
    } else {
        *(float4*)(out + off + c0) = make_float4(y[0], y[1], y[2], y[3]);
    }
}

// ---------------- launch ---------------------------------------------------
extern "C" void kernel_launch(void* const* d_in, const int* in_sizes, int n_in,
                              void* d_out, int out_size)
{
    (void)in_sizes; (void)n_in; (void)out_size;
    const float* x    = (const float*)d_in[0];
    const int*   mask = (const int*)  d_in[1];
    const float* Wq = (const float*)d_in[2];
    const float* bq = (const float*)d_in[3];
    const float* Wk = (const float*)d_in[4];
    const float* bk = (const float*)d_in[5];
    const float* Wv = (const float*)d_in[6];
    const float* bv = (const float*)d_in[7];
    const float* Wo = (const float*)d_in[8];
    const float* bo = (const float*)d_in[9];
    const float* W1 = (const float*)d_in[10];
    const float* b1 = (const float*)d_in[11];
    const float* W2 = (const float*)d_in[12];
    const float* b2 = (const float*)d_in[13];
    const float* g1 = (const float*)d_in[14];
    const float* be1= (const float*)d_in[15];
    const float* g2 = (const float*)d_in[16];
    const float* be2= (const float*)d_in[17];
    float* out = (float*)d_out;

    __half *tmp, *wt, *xh, *qh, *kh, *vh, *ctx, *x1h, *ffh;
    cudaGetSymbolAddress((void**)&tmp, g_tmp);
    cudaGetSymbolAddress((void**)&wt,  g_wt);
    cudaGetSymbolAddress((void**)&xh,  g_xh);
    cudaGetSymbolAddress((void**)&qh,  g_qh);
    cudaGetSymbolAddress((void**)&kh,  g_kh);
    cudaGetSymbolAddress((void**)&vh,  g_vh);
    cudaGetSymbolAddress((void**)&ctx, g_ctx);
    cudaGetSymbolAddress((void**)&x1h, g_x1h);
    cudaGetSymbolAddress((void**)&ffh, g_ffh);

    const int SM128 = 3 * (128 + 128) * 128;   // 98304 (3 stages)
    const int SM64  = 4 * (128 + 64) * 128;    // 98304 (4 stages)
    cudaFuncSetAttribute((const void*)sgemm_mma_kernel<0, 64>,
                         cudaFuncAttributeMaxDynamicSharedMemorySize, SM64);
    cudaFuncSetAttribute((const void*)sgemm_mma_kernel<3, 64>,
                         cudaFuncAttributeMaxDynamicSharedMemorySize, SM64);
    cudaFuncSetAttribute((const void*)sgemm_mma_kernel<1, 128>,
                         cudaFuncAttributeMaxDynamicSharedMemorySize, SM128);
    cudaFuncSetAttribute((const void*)sgemm_mma_kernel<2, 128>,
                         cudaFuncAttributeMaxDynamicSharedMemorySize, SM128);
    cudaFuncSetAttribute(attn_mma_kernel,
                         cudaFuncAttributeMaxDynamicSharedMemorySize, ATT_SMEM);

    const int M = NTOK;

    // fused prep: all weight transposes + x convert (one launch)
    prep_kernel<<<5120, 256>>>(Wq, Wk, Wv, Wo, W1, W2, x, wt, xh);

    // fused QKV projection (fp16 out, Q pre-scaled) — BN=128 (best measured)
    {
        dim3 grid(1536 / 128, M / 128);
        sgemm_mma_kernel<2, 128><<<grid, 256, SM128>>>(
            xh, wt + OFF_WQKV, bq, bk, bv, nullptr, nullptr,
            nullptr, qh, kh, vh, M, 1536, 512);
    }

    // flash attention (fp16 tensor cores, paired KV tiles)
    {
        dim3 grid(SEQ / 128, N_HEADS, BATCH);
        attn_mma_kernel<<<grid, 256, ATT_SMEM>>>(qh, kh, vh, mask, ctx);
    }

    // Wo projection (+bias +fp32 residual x) -> fp16 tmp; x1h = LN(tmp)
    {
        dim3 grid(512 / 64, M / 128);
        sgemm_mma_kernel<0, 64><<<grid, 256, SM64>>>(
            ctx, wt + OFF_WO, bo, nullptr, nullptr, x, nullptr,
            tmp, nullptr, nullptr, nullptr, M, 512, 512);
        ln_kernel<true><<<M, 128>>>(tmp, g1, be1, nullptr, x1h);
    }

    // FF
    {
        dim3 grid1(2048 / 128, M / 128);
        sgemm_mma_kernel<1, 128><<<grid1, 256, SM128>>>(
            x1h, wt + OFF_W1, b1, nullptr, nullptr, nullptr, nullptr,
            ffh, nullptr, nullptr, nullptr, M, 2048, 512);
        dim3 grid2(512 / 64, M / 128);
        sgemm_mma_kernel<3, 64><<<grid2, 256, SM64>>>(
            ffh, wt + OFF_W2, b2, nullptr, nullptr, nullptr, x1h,
            tmp, nullptr, nullptr, nullptr, M, 512, 2048);
        ln_kernel<false><<<M, 128>>>(tmp, g2, be2, out, nullptr);
    }
}

// round 17
// speedup vs baseline: 1.0359x; 1.0205x over previous
#include <cuda_runtime.h>
#include <cuda_fp16.h>
#include <cstdint>
#include <math.h>

#define D_MODEL 512
#define N_HEADS 8
#define DK      64
#define D_FF    2048
#define BATCH   2
#define SEQ     2048
#define NTOK    (BATCH * SEQ)   // 4096

#define SCALE_Q 0.18033688011112042f   // 0.125 * log2(e)

// ---------------- scratch (device globals; no allocation allowed) ----------
static __device__ __half g_tmp[(size_t)NTOK * D_MODEL];   // fp16 glue buffer

static __device__ __half g_xh [(size_t)NTOK * D_MODEL];
static __device__ __half g_qh [(size_t)NTOK * D_MODEL];
static __device__ __half g_kh [(size_t)NTOK * D_MODEL];
static __device__ __half g_vh [(size_t)NTOK * D_MODEL];
static __device__ __half g_ctx[(size_t)NTOK * D_MODEL];
static __device__ __half g_x1h[(size_t)NTOK * D_MODEL];
static __device__ __half g_ffh[(size_t)NTOK * D_FF];

// transposed fp16 weights: Wt[n][k]; WQ/WK/WV contiguous -> fused [1536,512]
#define OFF_WQKV 0
#define OFF_WO   (3*512*512)
#define OFF_W1   (4*512*512)
#define OFF_W2   (4*512*512 + 2048*512)
#define WT_TOTAL (4*512*512 + 2*2048*512)
static __device__ __half g_wt[WT_TOTAL];

// ======================= PTX helpers (base sm_80+ features) ================
__device__ __forceinline__ uint32_t smem_u32(const void* p) {
    uint32_t a;
    asm("{ .reg .u64 t; cvta.to.shared.u64 t, %1; cvt.u32.u64 %0, t; }"
        : "=r"(a) : "l"(p));
    return a;
}
__device__ __forceinline__ void cp_async16(uint32_t dst, const void* src) {
    asm volatile("cp.async.cg.shared.global [%0], [%1], 16;" :: "r"(dst), "l"(src));
}
#define CP_COMMIT() asm volatile("cp.async.commit_group;" ::: "memory")
#define CP_WAIT1()  asm volatile("cp.async.wait_group 1;" ::: "memory")
#define CP_WAIT2()  asm volatile("cp.async.wait_group 2;" ::: "memory")

__device__ __forceinline__ void ldm_x4(uint32_t* r, uint32_t addr) {
    asm volatile("ldmatrix.sync.aligned.m8n8.x4.shared.b16 {%0,%1,%2,%3}, [%4];"
        : "=r"(r[0]), "=r"(r[1]), "=r"(r[2]), "=r"(r[3]) : "r"(addr));
}
__device__ __forceinline__ void ldm_x4_t(uint32_t* r, uint32_t addr) {
    asm volatile("ldmatrix.sync.aligned.m8n8.x4.trans.shared.b16 {%0,%1,%2,%3}, [%4];"
        : "=r"(r[0]), "=r"(r[1]), "=r"(r[2]), "=r"(r[3]) : "r"(addr));
}
__device__ __forceinline__ void mma_f16(float* c, const uint32_t* a, const uint32_t* b) {
    asm volatile("mma.sync.aligned.m16n8k16.row.col.f32.f16.f16.f32 "
        "{%0,%1,%2,%3}, {%4,%5,%6,%7}, {%8,%9}, {%0,%1,%2,%3};"
        : "+f"(c[0]), "+f"(c[1]), "+f"(c[2]), "+f"(c[3])
        : "r"(a[0]), "r"(a[1]), "r"(a[2]), "r"(a[3]), "r"(b[0]), "r"(b[1]));
}
// pack (lo, hi) -> f16x2 (lo in low half)
__device__ __forceinline__ uint32_t pack_f16x2(float lo, float hi) {
    uint32_t r;
    asm("cvt.rn.f16x2.f32 %0, %1, %2;" : "=r"(r) : "f"(hi), "f"(lo));
    return r;
}
// packed fp16x2 exp2 on MUFU (sm_75+)
__device__ __forceinline__ uint32_t ex2_f16x2(uint32_t x) {
    uint32_t r;
    asm("ex2.approx.f16x2 %0, %1;" : "=r"(r) : "r"(x));
    return r;
}
// PDL intrinsics (sm_90+)
__device__ __forceinline__ void pdl_wait() {
    asm volatile("griddepcontrol.wait;" ::: "memory");
}
__device__ __forceinline__ void pdl_trigger() {
    asm volatile("griddepcontrol.launch_dependents;" ::: "memory");
}

// fast exp2 for x <= 0 on the FMA pipe (no MUFU). abs err ~2e-6.
__device__ __forceinline__ float exp2p(float x) {
    x = fmaxf(x, -126.f);
    float t = __fadd_rn(x, 12582912.f);
    float n = __fadd_rn(t, -12582912.f);
    float f = x - n;
    float p = 1.3333558146e-3f;
    p = fmaf(p, f, 9.6181291077e-3f);
    p = fmaf(p, f, 5.5504108665e-2f);
    p = fmaf(p, f, 2.4022650696e-1f);
    p = fmaf(p, f, 6.9314718056e-1f);
    p = fmaf(p, f, 1.0f);
    int e = __float_as_int(t) - 0x4B400000;
    return p * __int_as_float((e + 127) << 23);
}

// ============ fused prep: 6 weight transposes + x fp32->fp16 ================
__device__ __forceinline__ void transpose_tile32(const float* __restrict__ W,
                                                 __half* __restrict__ T,
                                                 int K, int N, int k0, int n0,
                                                 float* tile /* 32*33 */)
{
    const int tx = threadIdx.x & 31, ty = threadIdx.x >> 5;
    for (int i = ty; i < 32; i += 8)
        tile[i * 33 + tx] = W[(size_t)(k0 + i) * N + n0 + tx];
    __syncthreads();
    for (int i = ty; i < 32; i += 8)
        T[(size_t)(n0 + i) * K + k0 + tx] = __float2half(tile[tx * 33 + i]);
}

__global__ void prep_kernel(const float* __restrict__ Wq,
                            const float* __restrict__ Wk,
                            const float* __restrict__ Wv,
                            const float* __restrict__ Wo,
                            const float* __restrict__ W1,
                            const float* __restrict__ W2,
                            const float* __restrict__ x,
                            __half* __restrict__ wt,
                            __half* __restrict__ xh)
{
    __shared__ float tile[32 * 33];
    const int bid = blockIdx.x;
    if (bid < 1024) {
        const int z = bid >> 8, t = bid & 255;
        const float* W = (z == 0) ? Wq : (z == 1) ? Wk : (z == 2) ? Wv : Wo;
        transpose_tile32(W, wt + (size_t)z * 512 * 512, 512, 512,
                         (t >> 4) * 32, (t & 15) * 32, tile);
    } else if (bid < 2048) {
        const int t = bid - 1024;
        transpose_tile32(W1, wt + OFF_W1, 512, 2048,
                         (t >> 6) * 32, (t & 63) * 32, tile);
    } else if (bid < 3072) {
        const int t = bid - 2048;
        transpose_tile32(W2, wt + OFF_W2, 2048, 512,
                         (t >> 4) * 32, (t & 15) * 32, tile);
    } else {
        const int i = (bid - 3072) * 1024 + threadIdx.x * 4;
        float4 v = *(const float4*)(x + i);
        *(uint2*)(xh + i) = make_uint2(pack_f16x2(v.x, v.y), pack_f16x2(v.z, v.w));
    }
}

// ================ fp16 tensor-core GEMM: C = A @ B^T + bias =================
// A fp16 [M,K] row-major; B fp16 [N,K] K-major. fp32 accumulate.
// BK=64, 128-byte swizzled smem rows.
//   BN=128: 3-stage ring (warp grid 2x4, tile 64x32).
//   BN=64 : 4-stage ring, paired chunks, one wait per 2 chunks (4x2, 32x32).
// PDL: pdl_wait() gates consumption of predecessor data. PREB kernels preload
// their B (weight) prologue stages BEFORE the wait — transitively safe since a
// triggered producer has itself passed its own wait (=> prep completed).
// MODE 0: fp16 out (+bias + fp32 residual)   [Wo]
// MODE 1: fp16 out (+bias, +relu)            [FF1]
// MODE 2: fused QKV (N=1536), per-section bias+scale
// MODE 3: fp16 out (+bias + fp16 residual)   [FF2]
#define ATILEB (128 * 128)        // A tile bytes per stage (16384)

template <int MODE, int BN, bool PREB>
__launch_bounds__(256, 2)
__global__ void sgemm_mma_kernel(const __half* __restrict__ A,
                                 const __half* __restrict__ B,
                                 const float* __restrict__ bias0,
                                 const float* __restrict__ bias1,
                                 const float* __restrict__ bias2,
                                 const float* __restrict__ Res,
                                 const __half* __restrict__ ResH,
                                 __half* __restrict__ Ch,
                                 __half* __restrict__ Qd,
                                 __half* __restrict__ Kd,
                                 __half* __restrict__ Vd,
                                 int M, int N, int K)
{
    constexpr int WM = (BN == 128) ? 2 : 4;    // warps along M
    constexpr int MI = 128 / (WM * 16);        // m16 tiles per warp
    constexpr int GSTAGE = (128 + BN) * 128;   // stage bytes
    constexpr int NSTAGES = (BN == 64) ? 4 : 3;

    extern __shared__ char smem[];
    const uint32_t sb = smem_u32(smem);
    const int tid = threadIdx.x;
    const int lane = tid & 31, wid = tid >> 5;
    const int wm = wid % WM, wn = wid / WM;
    const int bm = blockIdx.y * 128;
    const int bn = blockIdx.x * BN;

    const uint32_t rowA0 = (uint32_t)(wm * (MI * 16) + (lane & 15));
    const uint32_t cA    = (uint32_t)(lane >> 4);
    const uint32_t rowB0 = (uint32_t)(wn * 32 + ((lane & 16) ? 8 : 0) + (lane & 7));
    const uint32_t cB    = (uint32_t)((lane & 8) ? 1 : 0);
    const uint32_t l7    = (uint32_t)(lane & 7);

    const __half* aBase = A + (size_t)bm * K;
    const __half* bBase = B + (size_t)bn * K;

    const int nchunks = K >> 6;

    auto load_A = [&](int s, int c) {           // A: 128 rows x 8 chunks = 1024
        const int k0 = c << 6;
        const uint32_t stg = sb + s * GSTAGE;
#pragma unroll
        for (int i = 0; i < 4; i++) {
            int idx = i * 256 + tid;
            int r = idx >> 3, ch = idx & 7;
            cp_async16(stg + (uint32_t)r * 128 + (uint32_t)((ch ^ (r & 7)) << 4),
                       aBase + (size_t)r * K + k0 + ch * 8);
        }
    };
    auto load_B = [&](int s, int c) {           // B: BN rows x 8 chunks
        const int k0 = c << 6;
        const uint32_t stg = sb + s * GSTAGE + ATILEB;
#pragma unroll
        for (int i = 0; i < BN * 8 / 256; i++) {
            int idx = i * 256 + tid;
            int r = idx >> 3, ch = idx & 7;
            cp_async16(stg + (uint32_t)r * 128 + (uint32_t)((ch ^ (r & 7)) << 4),
                       bBase + (size_t)r * K + k0 + ch * 8);
        }
    };
    auto load_stage = [&](int s, int c) { load_A(s, c); load_B(s, c); };

    // -------- prologue: PDL-overlapped --------
    if (PREB) {
        // weight preload BEFORE the dependency wait (producer-independent)
#pragma unroll
        for (int s = 0; s < NSTAGES - (BN == 128 ? 1 : 0); s++)
            load_B(s, s);
        pdl_wait();
#pragma unroll
        for (int s = 0; s < NSTAGES - (BN == 128 ? 1 : 0); s++) {
            load_A(s, s);
            CP_COMMIT();
        }
    } else {
        pdl_wait();
        if (BN == 64) {
            load_stage(0, 0); CP_COMMIT();
            load_stage(1, 1); CP_COMMIT();
            load_stage(2, 2); CP_COMMIT();
            load_stage(3, 3); CP_COMMIT();
        } else {
            load_stage(0, 0); CP_COMMIT();
            load_stage(1, 1); CP_COMMIT();
        }
    }

    float acc[MI][4][4];
#pragma unroll
    for (int i = 0; i < MI; i++)
#pragma unroll
        for (int j = 0; j < 4; j++)
#pragma unroll
            for (int t = 0; t < 4; t++) acc[i][j][t] = 0.f;

    auto compute_chunk = [&](uint32_t base) {
#pragma unroll
        for (int kst = 0; kst < 4; kst++) {
            const uint32_t swA = ((kst * 2 + cA) ^ l7) << 4;
            const uint32_t swB = ((kst * 2 + cB) ^ l7) << 4;
            uint32_t fa[MI][4], fb[2][4];
#pragma unroll
            for (int i = 0; i < MI; i++)
                ldm_x4(fa[i], base + (rowA0 + i * 16) * 128 + swA);
#pragma unroll
            for (int jj = 0; jj < 2; jj++)
                ldm_x4(fb[jj], base + ATILEB + (rowB0 + jj * 16) * 128 + swB);
#pragma unroll
            for (int i = 0; i < MI; i++)
#pragma unroll
                for (int j = 0; j < 4; j++)
                    mma_f16(acc[i][j], fa[i], &fb[j >> 1][(j & 1) * 2]);
        }
    };

    if (BN == 64) {
        // 4-stage ring, paired chunks (nchunks is a multiple of 4 here)
        for (int it = 0; it < nchunks / 2; it++) {
            const int kt = it * 2;
            CP_WAIT2();
            __syncthreads();
            compute_chunk(sb + (uint32_t)(kt & 3) * GSTAGE);
            compute_chunk(sb + (uint32_t)((kt + 1) & 3) * GSTAGE);
            __syncthreads();
            if (kt + 4 < nchunks) load_stage(kt & 3, kt + 4);
            CP_COMMIT();                       // unconditional: keeps accounting
            if (kt + 5 < nchunks) load_stage((kt + 1) & 3, kt + 5);
            CP_COMMIT();
        }
    } else {
        int s = 0;
        for (int c = 0; c < nchunks; c++) {
            CP_WAIT1();
            __syncthreads();

            int sw = s + 2; if (sw >= 3) sw -= 3;
            if (c + 2 < nchunks) load_stage(sw, c + 2);
            CP_COMMIT();                       // unconditional

            compute_chunk(sb + (uint32_t)s * GSTAGE);
            if (++s == 3) s = 0;
        }
    }

    pdl_trigger();                             // consumer may begin launching

    // -------- epilogue --------
    const int tr = lane >> 2;
    const int tc2 = (lane & 3) * 2;

    const float* biasS = bias0;
    __half* dstS = Qd;
    float scaleS = 1.f;
    if (MODE == 2) {
        const int sec = bn >> 9;
        biasS  = (sec == 0) ? bias0 : (sec == 1) ? bias1 : bias2;
        dstS   = (sec == 0) ? Qd : (sec == 1) ? Kd : Vd;
        scaleS = (sec == 0) ? SCALE_Q : 1.f;
    }

#pragma unroll
    for (int i = 0; i < MI; i++) {
#pragma unroll
        for (int j = 0; j < 4; j++) {
            const int r = bm + wm * (MI * 16) + i * 16 + tr;
            const int ncol = bn + wn * 32 + j * 8 + tc2;
#pragma unroll
            for (int half = 0; half < 2; half++) {
                float v0 = acc[i][j][half * 2 + 0];
                float v1 = acc[i][j][half * 2 + 1];
                const size_t row = (size_t)(r + half * 8);
                if (MODE == 0 || MODE == 3) {
                    float r0, r1;
                    if (MODE == 0) {
                        float2 rv = *(const float2*)(Res + row * N + ncol);
                        r0 = rv.x; r1 = rv.y;
                    } else {
                        __half2 rh = *(const __half2*)(ResH + row * N + ncol);
                        float2 rv = __half22float2(rh);
                        r0 = rv.x; r1 = rv.y;
                    }
                    v0 += bias0[ncol] + r0;
                    v1 += bias0[ncol + 1] + r1;
                    *(uint32_t*)(Ch + row * N + ncol) = pack_f16x2(v0, v1);
                } else if (MODE == 1) {
                    v0 = fmaxf(v0 + bias0[ncol], 0.f);
                    v1 = fmaxf(v1 + bias0[ncol + 1], 0.f);
                    *(uint32_t*)(Ch + row * N + ncol) = pack_f16x2(v0, v1);
                } else {
                    const int col = ncol & 511;
                    v0 = (v0 + biasS[col]) * scaleS;
                    v1 = (v1 + biasS[col + 1]) * scaleS;
                    *(uint32_t*)(dstS + row * 512 + col) = pack_f16x2(v0, v1);
                }
            }
        }
    }
}

// ================== tensor-core flash attention (fp16) ======================
// 128 q-rows per CTA, 8 warps, kv tiles of 64 processed in pairs (4 stages,
// one wait + one barrier pair per 2 tiles). Unconditional commits. PDL: mask
// table built pre-wait; Q/KV loads post-wait; trigger before the epilogue.
#define ATT_KVOFF 24576
#define ATT_SMEM (8192 + 16384 + 4 * 16384)   // 90112

__launch_bounds__(256, 2)
__global__ void attn_mma_kernel(const __half* __restrict__ qh,
                                const __half* __restrict__ kh,
                                const __half* __restrict__ vh,
                                const int* __restrict__ mask,
                                __half* __restrict__ ctx)
{
    extern __shared__ char smc[];
    const uint32_t sb = smem_u32(smc);
    const int tid = threadIdx.x, lane = tid & 31, w = tid >> 5;
    const int qt = blockIdx.x, h = blockIdx.y, b = blockIdx.z;
    const int q0 = qt * 128;
    const size_t qbase  = ((size_t)(b * SEQ + q0)) * D_MODEL + h * DK;
    const size_t kvbase = ((size_t)(b * SEQ)) * D_MODEL + h * DK;

    // pre-wait: mask table (harness input, independent of predecessor)
    float* madd = (float*)smc;
    for (int i = tid; i < SEQ; i += 256)
        madd[i] = (mask[b * SEQ + i] == 0) ? -1e9f : 0.f;

    pdl_wait();

    auto load_kv = [&](int stg_i, int ktile) {
        const uint32_t stg = sb + ATT_KVOFF + stg_i * 16384;
        const size_t tokbase = kvbase + (size_t)ktile * 64 * D_MODEL;
        const __half* srcs[2] = { kh + tokbase, vh + tokbase };
#pragma unroll
        for (int i = 0; i < 4; i++) {
            int idx = i * 256 + tid;
            int t2 = idx >> 9;
            int rem = idx & 511;
            int r = rem >> 3, c = rem & 7;
            uint32_t off = (uint32_t)r * 128 + (uint32_t)((c ^ (r & 7)) << 4);
            cp_async16(stg + t2 * 8192 + off, srcs[t2] + (size_t)r * D_MODEL + c * 8);
        }
    };

    // prologue: Q (with kv0's group) + kv1..kv3
#pragma unroll
    for (int i = 0; i < 4; i++) {
        int idx = i * 256 + tid;
        int r = idx >> 3, c = idx & 7;
        uint32_t off = (uint32_t)r * 128 + (uint32_t)((c ^ (r & 7)) << 4);
        cp_async16(sb + 8192 + off, qh + qbase + (size_t)r * D_MODEL + c * 8);
    }
    load_kv(0, 0);
    CP_COMMIT();
    load_kv(1, 1);
    CP_COMMIT();
    load_kv(2, 2);
    CP_COMMIT();
    load_kv(3, 3);
    CP_COMMIT();

    CP_WAIT2();          // Q + kv0, kv1 complete
    __syncthreads();

    // Q fragments (registers for whole kernel)
    uint32_t qf[4][4];
    {
        const uint32_t qrow = (uint32_t)(w * 16 + (lane & 15));
        const uint32_t qc = (uint32_t)(lane >> 4);
#pragma unroll
        for (int ks = 0; ks < 4; ks++) {
            uint32_t c16 = ks * 2 + qc;
            uint32_t off = qrow * 128 + ((c16 ^ (qrow & 7)) << 4);
            ldm_x4(qf[ks], sb + 8192 + off);
        }
    }

    float m0 = -1e30f, m1 = -1e30f, l0 = 0.f, l1 = 0.f;
    float O[8][4];
#pragma unroll
    for (int g = 0; g < 8; g++)
#pragma unroll
        for (int t = 0; t < 4; t++) O[g][t] = 0.f;

    const uint32_t kr_base = (uint32_t)(((lane & 16) ? 8 : 0) + (lane & 7));
    const uint32_t kc_add  = (uint32_t)((lane & 8) ? 1 : 0);
    const uint32_t vr_base = (uint32_t)(lane & 15);
    const uint32_t vc_add  = (uint32_t)(lane >> 4);

    auto do_tile = [&](int kt, uint32_t stg) {
        float S[8][4];
#pragma unroll
        for (int g = 0; g < 8; g++)
#pragma unroll
            for (int t = 0; t < 4; t++) S[g][t] = 0.f;

#pragma unroll
        for (int tg = 0; tg < 4; tg++) {
            const uint32_t row = tg * 16 + kr_base;
#pragma unroll
            for (int ks = 0; ks < 4; ks++) {
                uint32_t c16 = ks * 2 + kc_add;
                uint32_t off = row * 128 + ((c16 ^ (row & 7)) << 4);
                uint32_t fh[4];
                ldm_x4(fh, stg + off);
                mma_f16(S[2 * tg],     qf[ks], &fh[0]);
                mma_f16(S[2 * tg + 1], qf[ks], &fh[2]);
            }
        }

        float mt0 = -1e30f, mt1 = -1e30f;
#pragma unroll
        for (int g = 0; g < 8; g++) {
            float2 ma = *(float2*)&madd[kt * 64 + g * 8 + (lane & 3) * 2];
            S[g][0] += ma.x; S[g][1] += ma.y;
            S[g][2] += ma.x; S[g][3] += ma.y;
            mt0 = fmaxf(mt0, fmaxf(S[g][0], S[g][1]));
            mt1 = fmaxf(mt1, fmaxf(S[g][2], S[g][3]));
        }
        mt0 = fmaxf(mt0, __shfl_xor_sync(0xffffffffu, mt0, 1));
        mt0 = fmaxf(mt0, __shfl_xor_sync(0xffffffffu, mt0, 2));
        mt1 = fmaxf(mt1, __shfl_xor_sync(0xffffffffu, mt1, 1));
        mt1 = fmaxf(mt1, __shfl_xor_sync(0xffffffffu, mt1, 2));

        if (__any_sync(0xffffffffu, (mt0 > m0) | (mt1 > m1))) {
            const float mn0 = fmaxf(m0, mt0), mn1 = fmaxf(m1, mt1);
            const float a0 = exp2p(m0 - mn0), a1 = exp2p(m1 - mn1);
            m0 = mn0; m1 = mn1;
            l0 *= a0; l1 *= a1;
#pragma unroll
            for (int g = 0; g < 8; g++) {
                O[g][0] *= a0; O[g][1] *= a0;
                O[g][2] *= a1; O[g][3] *= a1;
            }
        }

        float s0 = 0.f, s1 = 0.f;
        uint32_t ph[4][4];
#pragma unroll
        for (int g = 0; g < 8; g++) {
            uint32_t p01 = ex2_f16x2(pack_f16x2(S[g][0] - m0, S[g][1] - m0));
            uint32_t p23 = ex2_f16x2(pack_f16x2(S[g][2] - m1, S[g][3] - m1));
            float2 f01 = __half22float2(*(__half2*)&p01);
            float2 f23 = __half22float2(*(__half2*)&p23);
            s0 += f01.x + f01.y;
            s1 += f23.x + f23.y;
            ph[g >> 1][(g & 1) * 2 + 0] = p01;
            ph[g >> 1][(g & 1) * 2 + 1] = p23;
        }
        s0 += __shfl_xor_sync(0xffffffffu, s0, 1);
        s0 += __shfl_xor_sync(0xffffffffu, s0, 2);
        s1 += __shfl_xor_sync(0xffffffffu, s1, 1);
        s1 += __shfl_xor_sync(0xffffffffu, s1, 2);
        l0 += s0;
        l1 += s1;

#pragma unroll
        for (int gp = 0; gp < 4; gp++) {
#pragma unroll
            for (int j2 = 0; j2 < 4; j2++) {
                uint32_t row = j2 * 16 + vr_base;
                uint32_t c16 = gp * 2 + vc_add;
                uint32_t off = row * 128 + ((c16 ^ (row & 7)) << 4);
                uint32_t fh[4];
                ldm_x4_t(fh, stg + 8192 + off);
                mma_f16(O[2 * gp],     ph[j2], &fh[0]);
                mma_f16(O[2 * gp + 1], ph[j2], &fh[2]);
            }
        }
    };

    // mainloop: 2 tiles per iteration, 4-stage ring, one wait + one sync pair
    for (int it = 0; it < SEQ / 128; it++) {
        const int kt = it * 2;
        if (it > 0) { CP_WAIT2(); __syncthreads(); }
        const int sA = kt & 3, sB = (kt + 1) & 3;

        do_tile(kt,     sb + ATT_KVOFF + sA * 16384);
        do_tile(kt + 1, sb + ATT_KVOFF + sB * 16384);

        __syncthreads();
        if (kt + 4 < SEQ / 64) load_kv(sA, kt + 4);
        CP_COMMIT();                          // unconditional: exact accounting
        if (kt + 5 < SEQ / 64) load_kv(sB, kt + 5);
        CP_COMMIT();
    }

    pdl_trigger();

    // ---- epilogue: normalize + fp16 store ----
    const float inv0 = 1.f / l0, inv1 = 1.f / l1;
    const int rg = q0 + w * 16 + (lane >> 2);
    const size_t ob = ((size_t)(b * SEQ)) * D_MODEL + h * DK;
#pragma unroll
    for (int g = 0; g < 8; g++) {
        const int col = g * 8 + (lane & 3) * 2;
        *(uint32_t*)(ctx + ob + (size_t)rg * D_MODEL + col) =
            pack_f16x2(O[g][0] * inv0, O[g][1] * inv0);
        *(uint32_t*)(ctx + ob + (size_t)(rg + 8) * D_MODEL + col) =
            pack_f16x2(O[g][2] * inv1, O[g][3] * inv1);
    }
}

// -------- LayerNorm over fp16 sum buffer --------
// H16OUT: write fp16 (feeds next GEMM). else: write fp32 (final output).
template <bool H16OUT>
__launch_bounds__(128)
__global__ void ln_kernel(const __half* __restrict__ a,
                          const float* __restrict__ g,
                          const float* __restrict__ beta,
                          float* __restrict__ out,
                          __half* __restrict__ oh)
{
    const int row = blockIdx.x;
    const int tid = threadIdx.x;
    const size_t off = (size_t)row * D_MODEL;
    const int c0 = tid * 4;

    pdl_wait();

    uint2 raw = *(const uint2*)(a + off + c0);
    float2 f01 = __half22float2(*(__half2*)&raw.x);
    float2 f23 = __half22float2(*(__half2*)&raw.y);
    float v[4] = { f01.x, f01.y, f23.x, f23.y };

    float s = v[0] + v[1] + v[2] + v[3];
    float ss = v[0] * v[0] + v[1] * v[1] + v[2] * v[2] + v[3] * v[3];
#pragma unroll
    for (int o = 16; o > 0; o >>= 1) {
        s  += __shfl_xor_sync(0xffffffffu, s, o);
        ss += __shfl_xor_sync(0xffffffffu, ss, o);
    }
    __shared__ float rs[4], rss[4];
    int w = tid >> 5, lane = tid & 31;
    if (lane == 0) { rs[w] = s; rss[w] = ss; }
    __syncthreads();
    s  = rs[0]  + rs[1]  + rs[2]  + rs[3];
    ss = rss[0] + rss[1] + rss[2] + rss[3];
    float mu   = s * (1.f / D_MODEL);
    float var  = ss * (1.f / D_MODEL) - mu * mu;
    float rstd = rsqrtf(var + 1e-5f);

    float y[4];
#pragma unroll
    for (int i = 0; i < 4; i++)
        y[i] = (v[i] - mu) * rstd * g[c0 + i] + beta[c0 + i];

    pdl_trigger();

    if (H16OUT) {
        *(uint2*)(oh + off + c0) =
            make_uint2(pack_f16x2(y[0], y[1]), pack_f16x2(y[2], y[3]));
    } else {
        *(float4*)(out + off + c0) = make_float4(y[0], y[1], y[2], y[3]);
    }
}

// ---------------- launch ---------------------------------------------------
#define LAUNCH_PDL(kern, grd, blk, smemBytes, ...) do {                        \
    cudaLaunchAttribute _a[1];                                                 \
    _a[0].id = cudaLaunchAttributeProgrammaticStreamSerialization;             \
    _a[0].val.programmaticStreamSerializationAllowed = 1;                      \
    cudaLaunchConfig_t _c;                                                     \
    _c.gridDim = grd; _c.blockDim = blk; _c.dynamicSmemBytes = smemBytes;      \
    _c.stream = 0; _c.attrs = _a; _c.numAttrs = 1;                             \
    cudaLaunchKernelEx(&_c, kern, __VA_ARGS__);                                \
} while (0)

extern "C" void kernel_launch(void* const* d_in, const int* in_sizes, int n_in,
                              void* d_out, int out_size)
{
    (void)in_sizes; (void)n_in; (void)out_size;
    const float* x    = (const float*)d_in[0];
    const int*   mask = (const int*)  d_in[1];
    const float* Wq = (const float*)d_in[2];
    const float* bq = (const float*)d_in[3];
    const float* Wk = (const float*)d_in[4];
    const float* bk = (const float*)d_in[5];
    const float* Wv = (const float*)d_in[6];
    const float* bv = (const float*)d_in[7];
    const float* Wo = (const float*)d_in[8];
    const float* bo = (const float*)d_in[9];
    const float* W1 = (const float*)d_in[10];
    const float* b1 = (const float*)d_in[11];
    const float* W2 = (const float*)d_in[12];
    const float* b2 = (const float*)d_in[13];
    const float* g1 = (const float*)d_in[14];
    const float* be1= (const float*)d_in[15];
    const float* g2 = (const float*)d_in[16];
    const float* be2= (const float*)d_in[17];
    float* out = (float*)d_out;

    __half *tmp, *wt, *xh, *qh, *kh, *vh, *ctx, *x1h, *ffh;
    cudaGetSymbolAddress((void**)&tmp, g_tmp);
    cudaGetSymbolAddress((void**)&wt,  g_wt);
    cudaGetSymbolAddress((void**)&xh,  g_xh);
    cudaGetSymbolAddress((void**)&qh,  g_qh);
    cudaGetSymbolAddress((void**)&kh,  g_kh);
    cudaGetSymbolAddress((void**)&vh,  g_vh);
    cudaGetSymbolAddress((void**)&ctx, g_ctx);
    cudaGetSymbolAddress((void**)&x1h, g_x1h);
    cudaGetSymbolAddress((void**)&ffh, g_ffh);

    const int SM128 = 3 * (128 + 128) * 128;   // 98304 (3 stages)
    const int SM64  = 4 * (128 + 64) * 128;    // 98304 (4 stages)
    cudaFuncSetAttribute((const void*)sgemm_mma_kernel<0, 64, true>,
                         cudaFuncAttributeMaxDynamicSharedMemorySize, SM64);
    cudaFuncSetAttribute((const void*)sgemm_mma_kernel<3, 64, true>,
                         cudaFuncAttributeMaxDynamicSharedMemorySize, SM64);
    cudaFuncSetAttribute((const void*)sgemm_mma_kernel<1, 128, true>,
                         cudaFuncAttributeMaxDynamicSharedMemorySize, SM128);
    cudaFuncSetAttribute((const void*)sgemm_mma_kernel<2, 128, false>,
                         cudaFuncAttributeMaxDynamicSharedMemorySize, SM128);
    cudaFuncSetAttribute(attn_mma_kernel,
                         cudaFuncAttributeMaxDynamicSharedMemorySize, ATT_SMEM);

    const int M = NTOK;

    // fused prep: all weight transposes + x convert (first node, plain launch)
    prep_kernel<<<5120, 256>>>(Wq, Wk, Wv, Wo, W1, W2, x, wt, xh);

    // fused QKV projection (fp16 out, Q pre-scaled)
    LAUNCH_PDL((sgemm_mma_kernel<2, 128, false>),
               dim3(1536 / 128, M / 128), dim3(256), SM128,
               (const __half*)xh, (const __half*)(wt + OFF_WQKV),
               bq, bk, bv, (const float*)nullptr, (const __half*)nullptr,
               (__half*)nullptr, qh, kh, vh, M, 1536, 512);

    // flash attention (fp16 tensor cores, paired KV tiles)
    LAUNCH_PDL(attn_mma_kernel,
               dim3(SEQ / 128, N_HEADS, BATCH), dim3(256), ATT_SMEM,
               (const __half*)qh, (const __half*)kh, (const __half*)vh,
               mask, ctx);

    // Wo projection (+bias +fp32 residual x) -> fp16 tmp; x1h = LN(tmp)
    LAUNCH_PDL((sgemm_mma_kernel<0, 64, true>),
               dim3(512 / 64, M / 128), dim3(256), SM64,
               (const __half*)ctx, (const __half*)(wt + OFF_WO),
               bo, (const float*)nullptr, (const float*)nullptr,
               x, (const __half*)nullptr,
               tmp, (__half*)nullptr, (__half*)nullptr, (__half*)nullptr,
               M, 512, 512);
    LAUNCH_PDL(ln_kernel<true>, dim3(M), dim3(128), 0,
               (const __half*)tmp, g1, be1, (float*)nullptr, x1h);

    // FF
    LAUNCH_PDL((sgemm_mma_kernel<1, 128, true>),
               dim3(2048 / 128, M / 128), dim3(256), SM128,
               (const __half*)x1h, (const __half*)(wt + OFF_W1),
               b1, (const float*)nullptr, (const float*)nullptr,
               (const float*)nullptr, (const __half*)nullptr,
               ffh, (__half*)nullptr, (__half*)nullptr, (__half*)nullptr,
               M, 2048, 512);
    LAUNCH_PDL((sgemm_mma_kernel<3, 64, true>),
               dim3(512 / 64, M / 128), dim3(256), SM64,
               (const __half*)ffh, (const __half*)(wt + OFF_W2),
               b2, (const float*)nullptr, (const float*)nullptr,
               (const float*)nullptr, (const __half*)x1h,
               tmp, (__half*)nullptr, (__half*)nullptr, (__half*)nullptr,
               M, 512, 2048);
    LAUNCH_PDL(ln_kernel<false>, dim3(M), dim3(128), 0,
               (const __half*)tmp, g2, be2, out, (__half*)nullptr);
}